// round 3
// baseline (speedup 1.0000x reference)
#include <cuda_runtime.h>

#define NB 512
#define TT 1024
#define CC 64

typedef unsigned long long u64;

__device__ __forceinline__ u64 pk(float lo, float hi) {
    u64 r; asm("mov.b64 %0, {%1,%2};" : "=l"(r) : "f"(lo), "f"(hi)); return r;
}
__device__ __forceinline__ void upk(u64 v, float& lo, float& hi) {
    asm("mov.b64 {%0,%1}, %2;" : "=f"(lo), "=f"(hi) : "l"(v));
}
__device__ __forceinline__ u64 ffma2(u64 a, u64 b, u64 c) {
    u64 d; asm("fma.rn.f32x2 %0, %1, %2, %3;" : "=l"(d) : "l"(a), "l"(b), "l"(c)); return d;
}
__device__ __forceinline__ u64 fmul2(u64 a, u64 b) {
    u64 d; asm("mul.rn.f32x2 %0, %1, %2;" : "=l"(d) : "l"(a), "l"(b)); return d;
}
__device__ __forceinline__ u64 fadd2(u64 a, u64 b) {
    u64 d; asm("add.rn.f32x2 %0, %1, %2;" : "=l"(d) : "l"(a), "l"(b)); return d;
}
__device__ __forceinline__ float frcp(float x) {
    float r; asm("rcp.approx.f32 %0, %1;" : "=f"(r) : "f"(x)); return r;
}

__global__ void __launch_bounds__(128, 1) crf_fwd_kernel(
    const float* __restrict__ logits,   // [NB, TT, CC]
    const float* __restrict__ trans,    // [CC, CC]  trans[i][j] = score j->i
    const float* __restrict__ init,     // [CC]
    const int*   __restrict__ lengths,  // [NB]
    const int*   __restrict__ tags,     // [NB, TT]
    float*       __restrict__ out)      // [NB]
{
    __shared__ __align__(16) float wbuf[4][2][2 * CC];  // duplicated pairs, double-buffered

    const int wid  = threadIdx.x >> 5;
    const int lane = threadIdx.x & 31;
    const int g    = blockIdx.x * 4 + wid;          // grid=128 -> g in [0,512)

    const float* lg = logits + (size_t)g * TT * CC;
    const int len = lengths[g];                     // in [2, 1024]

    // ---- build packed E rows: EP[j] = { exp(trans[lane][j]), exp(trans[lane+32][j]) }
    u64 EP[CC];
    {
        const float4* r0 = (const float4*)(trans + lane * CC);
        const float4* r1 = (const float4*)(trans + (lane + 32) * CC);
        #pragma unroll
        for (int q = 0; q < 16; ++q) {
            float4 x0 = __ldg(r0 + q);
            float4 x1 = __ldg(r1 + q);
            EP[4*q+0] = pk(__expf(x0.x), __expf(x1.x));
            EP[4*q+1] = pk(__expf(x0.y), __expf(x1.y));
            EP[4*q+2] = pk(__expf(x0.z), __expf(x1.z));
            EP[4*q+3] = pk(__expf(x0.w), __expf(x1.w));
        }
    }

    // ---- w_0 = exp(init + logits[0]) (C_0 = 0), stored duplicated
    float w_lo, w_hi;
    {
        float a0 = __ldg(init + lane)      + __ldg(lg + lane);
        float a1 = __ldg(init + lane + 32) + __ldg(lg + lane + 32);
        w_lo = __expf(a0);
        w_hi = __expf(a1);
        float2* ws = (float2*)(&wbuf[wid][0][0]);
        ws[lane]      = make_float2(w_lo, w_lo);
        ws[lane + 32] = make_float2(w_hi, w_hi);
        __syncwarp();
    }

    // F for t=1 (len >= 2 always)
    u64 F = pk(__expf(__ldg(lg + CC + lane)), __expf(__ldg(lg + CC + 32 + lane)));
    u64 Rp = pk(1.0f, 1.0f);   // shift factor applied this step
    float lnApp = 0.0f;        // -ln(Rp), added to C when Rp is applied
    float cacc  = 0.0f;        // running shift C
    int buf = 0;

    for (int t = 1; t < len; ++t) {
        // prefetch logits[t+1] (clamped; redundant load on last iter is harmless)
        const int tn = (t + 1 < len) ? (t + 1) : t;
        const float Lp0 = __ldg(lg + tn * CC + lane);
        const float Lp1 = __ldg(lg + tn * CC + lane + 32);

        // ---- dot: D[i] = sum_j E[i][j] * w[j], packed over the two owned states
        const ulonglong2* wv = (const ulonglong2*)(&wbuf[wid][buf][0]);
        u64 a0 = 0ull, a1 = 0ull, a2 = 0ull, a3 = 0ull;
        #pragma unroll
        for (int q = 0; q < 32; q += 2) {
            ulonglong2 b0 = wv[q];       // {w_{2q} dup, w_{2q+1} dup}
            ulonglong2 b1 = wv[q + 1];
            a0 = ffma2(EP[2*q + 0], b0.x, a0);
            a1 = ffma2(EP[2*q + 1], b0.y, a1);
            a2 = ffma2(EP[2*q + 2], b1.x, a2);
            a3 = ffma2(EP[2*q + 3], b1.y, a3);
        }
        const u64 d = fadd2(fadd2(a0, a1), fadd2(a2, a3));

        // ---- w_t = D * exp(logit_t) * R   (linear-domain update, no exp/log on chain)
        const u64 w = fmul2(fmul2(d, F), Rp);
        upk(w, w_lo, w_hi);
        float2* ws = (float2*)(&wbuf[wid][buf ^ 1][0]);
        ws[lane]      = make_float2(w_lo, w_lo);
        ws[lane + 32] = make_float2(w_hi, w_hi);
        __syncwarp();
        buf ^= 1;

        // ---- off-critical-path bookkeeping
        cacc += lnApp;                          // account for the R applied this step
        // normalize the NEXT step by the actual stored w_t[0] (stable lag-1 scheme)
        float vb = __shfl_sync(0xffffffffu, w_lo, 0);
        // guard: keep normalizer finite/nonzero so frcp/log can't poison the chain
        vb = fminf(fmaxf(vb, 1e-30f), 1e30f);
        const float rn = frcp(vb);              // R for next step (latency hidden by next dot)
        lnApp = -__logf(rn);                    // exact ln of the factor actually applied
        Rp = pk(rn, rn);
        F  = pk(__expf(Lp0), __expf(Lp1));      // F for next step
    }

    // ---- logZ = C + ln( sum_j w_{L-1}[j] )
    float s = w_lo + w_hi;
    #pragma unroll
    for (int o = 16; o; o >>= 1) s += __shfl_xor_sync(0xffffffffu, s, o);
    const float logZ = cacc + __logf(s);

    // ---- gold path score (lane-parallel over t; order-free sum, fp32-safe)
    const int* tg = tags + (size_t)g * TT;
    const int tg0 = __ldg(tg);
    const float first = __ldg(init + tg0) + __ldg(lg + tg0);
    float gs = 0.0f;
    for (int t = 1 + lane; t < len; t += 32) {
        const int tc = __ldg(tg + t);
        const int tp = __ldg(tg + t - 1);
        gs += __ldg(trans + tc * CC + tp) + __ldg(lg + t * CC + tc);
    }
    #pragma unroll
    for (int o = 16; o; o >>= 1) gs += __shfl_xor_sync(0xffffffffu, gs, o);

    if (lane == 0) out[g] = logZ - (first + gs);
}

extern "C" void kernel_launch(void* const* d_in, const int* in_sizes, int n_in,
                              void* d_out, int out_size)
{
    const float* logits = (const float*)d_in[0];
    const float* trans  = (const float*)d_in[1];
    const float* init   = (const float*)d_in[2];
    const int*   lens   = (const int*)  d_in[3];
    const int*   tags   = (const int*)  d_in[4];
    float*       out    = (float*)d_out;

    crf_fwd_kernel<<<NB / 4, 128>>>(logits, trans, init, lens, tags, out);
}